// round 5
// baseline (speedup 1.0000x reference)
#include <cuda_runtime.h>
#include <cstdint>
#include <cstddef>

#define BATCH 8
#define CCH   512
#define M2    1024          // 2*C rows of P
#define KDIM  4096
#define NTILES 8            // M2 / 128
#define NSTAGES 3
#define TILE_BYTES (128 * 128)          // 16KB: 128 rows x 128B (32 tf32), SW128 image
#define STAGE_BYTES (4 * TILE_BYTES)    // x_A, x_B, lo_A, lo_B
#define NKB   (KDIM / 32)               // 128 k-blocks of 32 tf32

// idesc kind::tf32: dtype F32 (1<<4) | atype TF32 (2<<7) | btype TF32 (2<<10)
//                 | (N/8)<<17 | (M/16)<<24, K-major both sides
#define IDESC_TF32 0x08200910u

// Arch-specific ('a') feature gate: tcgen05 only exists in the sm_103a SASS pass.
#if defined(__CUDA_ARCH__) && (defined(__CUDA_ARCH_FEAT_SM103_ALL) || defined(__CUDA_ARCH_FEAT_SM100_ALL) || defined(__CUDA_ARCH_FEAT_SM101_ALL) || defined(__CUDA_ARCH_FEAT_SM110_ALL))
#define TC_OK 1
#else
#define TC_OK 0
#endif

// ---------------- scratch (static device globals; no allocation) ----------------
__device__ float          g_tile[(size_t)BATCH * 8 * NKB * 4096];  // 134 MB swizzled x images
__device__ float          g_S[(size_t)BATCH * M2 * M2];            // 32 MB  S = P P^T
__device__ float          g_w[(size_t)BATCH * CCH * CCH];
__device__ unsigned short g_idx[(size_t)BATCH * CCH * CCH];
__device__ int            g_cnt[BATCH * CCH];

// ======================= helpers =======================
__device__ __forceinline__ uint32_t smem_u32(const void* p) {
    uint32_t a;
    asm("{ .reg .u64 t; cvta.to.shared.u64 t, %1; cvt.u32.u64 %0, t; }" : "=r"(a) : "l"(p));
    return a;
}

// =======================================================================
// Kernel 0: pure swizzled-tile copy of x: [b][rowblk(8)][kblk(128)] ->
// 16KB SW128 image (128 rows x 32 tf32). hi/lo split happens in-SMEM
// inside the SYRK, halving both this kernel's writes and the SYRK's reads.
// =======================================================================
__global__ __launch_bounds__(256) void split_kernel(const float* __restrict__ x) {
    const size_t idx = (size_t)blockIdx.x * 256 + threadIdx.x;   // 8*1024*1024 float4s
    const int b   = (int)(idx >> 20);
    const int row = (int)((idx >> 10) & 1023);
    const int k4  = (int)(idx & 1023);

    size_t src;
    if (row < CCH) src = ((size_t)b * CCH + row) * KDIM + (size_t)k4 * 4;
    else           src = ((size_t)(BATCH + b) * CCH + (row - CCH)) * KDIM + (size_t)k4 * 4;

    const float4 v = *(const float4*)(x + src);

    const int rb = row >> 7, r = row & 127;
    const int kb = k4 >> 3;
    const uint32_t byte_off = (uint32_t)r * 128u + (uint32_t)(k4 & 7) * 16u;
    const uint32_t sw = byte_off ^ ((byte_off >> 3) & 0x70u);
    const size_t dst = ((((size_t)b * 8 + rb) * NKB) + kb) * 4096 + (sw >> 2);

    *(float4*)(g_tile + dst) = v;
}

// =======================================================================
// Kernel A: tcgen05 tf32 3-split SYRK, 128x128 tile per CTA, 256 threads.
//   thread 0          : bulk-copy producer (x tiles only)
//   threads 32..255   : per-stage hi/lo split in SMEM (224 workers)
//   thread 32         : also the MMA issuer
//   threads 1..31     : idle until epilogue
//   warps 0-3         : TMEM epilogue + mirror
// =======================================================================
#if TC_OK
__device__ __forceinline__ void mbar_init(uint32_t a, uint32_t cnt) {
    asm volatile("mbarrier.init.shared.b64 [%0], %1;" :: "r"(a), "r"(cnt) : "memory");
}
__device__ __forceinline__ void mbar_inval(uint32_t a) {
    asm volatile("mbarrier.inval.shared.b64 [%0];" :: "r"(a) : "memory");
}
__device__ __forceinline__ void mbar_expect_tx(uint32_t a, uint32_t bytes) {
    asm volatile("mbarrier.arrive.expect_tx.shared.b64 _, [%0], %1;" :: "r"(a), "r"(bytes) : "memory");
}
__device__ __forceinline__ void mbar_arrive(uint32_t a) {
    asm volatile("mbarrier.arrive.shared.b64 _, [%0];" :: "r"(a) : "memory");
}
__device__ __forceinline__ void mbar_wait(uint32_t a, uint32_t parity) {
    asm volatile(
        "{\n\t.reg .pred P;\n\t"
        "W%=:\n\t"
        "mbarrier.try_wait.parity.acquire.cta.shared::cta.b64 P, [%0], %1, 0x989680;\n\t"
        "@P bra.uni D%=;\n\t"
        "bra.uni W%=;\n\t"
        "D%=:\n\t}"
        :: "r"(a), "r"(parity) : "memory");
}
__device__ __forceinline__ void bulk_g2s(uint32_t dst, const void* src, uint32_t bytes, uint32_t mbar) {
    asm volatile(
        "cp.async.bulk.shared::cta.global.mbarrier::complete_tx::bytes [%0], [%1], %2, [%3];"
        :: "r"(dst), "l"(src), "r"(bytes), "r"(mbar) : "memory");
}
__device__ __forceinline__ uint64_t make_desc_sw128(uint32_t addr) {
    return ((uint64_t)2 << 61) | ((uint64_t)1 << 46) | ((uint64_t)64 << 32) |
           ((uint64_t)1 << 16) | (((uint64_t)(addr >> 4)) & 0x3FFF);
}
__device__ __forceinline__ void mma_tf32_ss(uint32_t d, uint64_t ad, uint64_t bd, uint32_t en) {
    asm volatile(
        "{\n\t.reg .pred p;\n\t"
        "setp.ne.u32 p, %4, 0;\n\t"
        "tcgen05.mma.cta_group::1.kind::tf32 [%0], %1, %2, %3, {%5,%5,%5,%5}, p;\n\t}"
        :: "r"(d), "l"(ad), "l"(bd), "r"(IDESC_TF32), "r"(en), "r"(0u) : "memory");
}
__device__ __forceinline__ void tc_commit(uint32_t mbar) {
    asm volatile(
        "tcgen05.commit.cta_group::1.mbarrier::arrive::one.shared::cluster.b64 [%0];"
        :: "r"(mbar) : "memory");
}
__device__ __forceinline__ float tf32_rna(float v) {
    uint32_t h; asm("cvt.rna.tf32.f32 %0, %1;" : "=r"(h) : "f"(v));
    return __uint_as_float(h);
}
#endif

__global__ __launch_bounds__(256, 1) void syrk_tc_kernel() {
#if TC_OK
    extern __shared__ char smem[];
    const uint32_t sb = smem_u32(smem);
    const uint32_t tb = (sb + 1023u) & ~1023u;            // 1024-aligned tile base
    const uint32_t ctl = tb + NSTAGES * STAGE_BYTES;      // control area
    const uint32_t mb_full  = ctl + 16;                   // 3 x 8B
    const uint32_t mb_empty = ctl + 16 + 24;              // 3 x 8B
    const uint32_t mb_ready = ctl + 16 + 48;              // 3 x 8B
    const uint32_t mb_done  = ctl + 16 + 72;

    const int tid = threadIdx.x;
    const int wid = tid >> 5, lid = tid & 31;

    const int b = blockIdx.y;
    int ti = 0, rem = blockIdx.x;
    while (rem >= NTILES - ti) { rem -= NTILES - ti; ti++; }
    const int tj = ti + rem;
    const bool diag = (ti == tj);

    if (wid == 0) {
        asm volatile("tcgen05.alloc.cta_group::1.sync.aligned.shared::cta.b32 [%0], %1;"
                     :: "r"(ctl), "r"(128u) : "memory");
    }
    if (tid == 0) {
        for (int s = 0; s < NSTAGES; s++) {
            mbar_init(mb_full + s * 8, 1);
            mbar_init(mb_empty + s * 8, 1);
            mbar_init(mb_ready + s * 8, 224);          // threads 32..255 arrive
        }
        mbar_init(mb_done, 1);
        asm volatile("fence.proxy.async.shared::cta;" ::: "memory");
    }
    __syncthreads();

    uint32_t tmem;
    asm volatile("ld.shared.b32 %0, [%1];" : "=r"(tmem) : "r"(ctl));

    const uint32_t txbytes = diag ? TILE_BYTES : (2 * TILE_BYTES);

    if (tid == 0) {
        // ---------------- producer: x tiles only ----------------
        const size_t tiA = (((size_t)b * 8 + ti) * NKB) * 4096;
        const size_t tiB = (((size_t)b * 8 + tj) * NKB) * 4096;
        int ph[NSTAGES] = {0, 0, 0};
        for (int kb = 0; kb < NKB; kb++) {
            const int s = kb % NSTAGES;
            if (kb >= NSTAGES) { mbar_wait(mb_empty + s * 8, ph[s]); ph[s] ^= 1; }
            const uint32_t st = tb + s * STAGE_BYTES;
            const uint32_t fb = mb_full + s * 8;
            mbar_expect_tx(fb, txbytes);
            bulk_g2s(st, g_tile + tiA + (size_t)kb * 4096, TILE_BYTES, fb);
            if (!diag)
                bulk_g2s(st + TILE_BYTES, g_tile + tiB + (size_t)kb * 4096, TILE_BYTES, fb);
        }
    } else if (tid >= 32) {
        // ---------------- workers (threads 32..255) + MMA issuer (thread 32) ----------------
        const int wt = tid - 32;                 // 0..223
        int phf[NSTAGES] = {0, 0, 0};
        int phr[NSTAGES] = {0, 0, 0};
        uint32_t en = 0;
        for (int kb = 0; kb < NKB; kb++) {
            const int s = kb % NSTAGES;
            const uint32_t st = tb + s * STAGE_BYTES;
            mbar_wait(mb_full + s * 8, phf[s]); phf[s] ^= 1;

            // split hi (in place) / lo (offset +2 tiles); swizzle-transparent
            float* xA  = (float*)(smem + (st - sb));
            float* loA = (float*)(smem + (st - sb) + 2 * TILE_BYTES);
            const int ntiles = diag ? 1 : 2;
            for (int t2 = 0; t2 < ntiles; t2++) {
                float4* xp  = (float4*)(xA  + t2 * 4096);
                float4* lp  = (float4*)(loA + t2 * 4096);
                #pragma unroll 1
                for (int i = wt; i < 1024; i += 224) {
                    float4 v = xp[i];
                    float4 h, l;
                    h.x = tf32_rna(v.x); l.x = tf32_rna(v.x - h.x);
                    h.y = tf32_rna(v.y); l.y = tf32_rna(v.y - h.y);
                    h.z = tf32_rna(v.z); l.z = tf32_rna(v.z - h.z);
                    h.w = tf32_rna(v.w); l.w = tf32_rna(v.w - h.w);
                    xp[i] = h;
                    lp[i] = l;
                }
            }
            asm volatile("fence.proxy.async.shared::cta;" ::: "memory");
            mbar_arrive(mb_ready + s * 8);

            if (tid == 32) {
                mbar_wait(mb_ready + s * 8, phr[s]); phr[s] ^= 1;
                const uint64_t dAh = make_desc_sw128(st);
                const uint64_t dAl = make_desc_sw128(st + 2 * TILE_BYTES);
                const uint64_t dBh = diag ? dAh : make_desc_sw128(st + TILE_BYTES);
                const uint64_t dBl = diag ? dAl : make_desc_sw128(st + 3 * TILE_BYTES);
                #pragma unroll
                for (int k = 0; k < 4; k++) {    // 4 k-steps of 8 tf32
                    mma_tf32_ss(tmem, dAh + k * 2, dBh + k * 2, en); en = 1;
                    mma_tf32_ss(tmem, dAh + k * 2, dBl + k * 2, 1);
                    mma_tf32_ss(tmem, dAl + k * 2, dBh + k * 2, 1);
                }
                tc_commit(mb_empty + s * 8);
            }
        }
        if (tid == 32) tc_commit(mb_done);
    }
    // threads 1..31 fall through to the epilogue wait

    // ---------------- epilogue ----------------
    mbar_wait(mb_done, 0);
    asm volatile("tcgen05.fence::after_thread_sync;" ::: "memory");

    const size_t Sb = (size_t)b * M2 * M2;
    const int r0 = ti * 128, c0 = tj * 128;

    if (wid < 4) {
        const int row = r0 + wid * 32 + lid;
        for (int cb = 0; cb < 4; cb++) {
            uint32_t d[32];
            asm volatile(
                "tcgen05.ld.sync.aligned.32x32b.x32.b32 "
                "{%0,%1,%2,%3,%4,%5,%6,%7,%8,%9,%10,%11,%12,%13,%14,%15,"
                "%16,%17,%18,%19,%20,%21,%22,%23,%24,%25,%26,%27,%28,%29,%30,%31}, [%32];"
                : "=r"(d[0]), "=r"(d[1]), "=r"(d[2]), "=r"(d[3]), "=r"(d[4]), "=r"(d[5]), "=r"(d[6]), "=r"(d[7]),
                  "=r"(d[8]), "=r"(d[9]), "=r"(d[10]), "=r"(d[11]), "=r"(d[12]), "=r"(d[13]), "=r"(d[14]), "=r"(d[15]),
                  "=r"(d[16]), "=r"(d[17]), "=r"(d[18]), "=r"(d[19]), "=r"(d[20]), "=r"(d[21]), "=r"(d[22]), "=r"(d[23]),
                  "=r"(d[24]), "=r"(d[25]), "=r"(d[26]), "=r"(d[27]), "=r"(d[28]), "=r"(d[29]), "=r"(d[30]), "=r"(d[31])
                : "r"(tmem + cb * 32));
            asm volatile("tcgen05.wait::ld.sync.aligned;" ::: "memory");

            float* dst = g_S + Sb + (size_t)row * M2 + c0 + cb * 32;
            #pragma unroll
            for (int q = 0; q < 8; q++) {
                float4 v = make_float4(__uint_as_float(d[q * 4 + 0]), __uint_as_float(d[q * 4 + 1]),
                                       __uint_as_float(d[q * 4 + 2]), __uint_as_float(d[q * 4 + 3]));
                *(float4*)(dst + q * 4) = v;
            }
            if (!diag) {
                #pragma unroll
                for (int j = 0; j < 32; j++)
                    g_S[Sb + (size_t)(c0 + cb * 32 + j) * M2 + row] = __uint_as_float(d[j]);
            }
        }
    }

    __syncthreads();
    if (tid == 0) {
        for (int s = 0; s < NSTAGES; s++) {
            mbar_inval(mb_full + s * 8); mbar_inval(mb_empty + s * 8); mbar_inval(mb_ready + s * 8);
        }
        mbar_inval(mb_done);
    }
    __syncthreads();
    if (wid == 0) {
        asm volatile("tcgen05.dealloc.cta_group::1.sync.aligned.b32 %0, %1;" :: "r"(tmem), "r"(128u));
    }
#endif
}

// =======================================================================
// Kernel B: softmax of (max-er)^2+(max-ei)^2 over S rows + compaction
// =======================================================================
__device__ __forceinline__ float blkReduce(float v, float* red, bool isMax) {
    #pragma unroll
    for (int o = 16; o > 0; o >>= 1) {
        float tv = __shfl_xor_sync(0xffffffffu, v, o);
        v = isMax ? fmaxf(v, tv) : (v + tv);
    }
    const int lane = threadIdx.x & 31, wid = threadIdx.x >> 5;
    if (lane == 0) red[wid] = v;
    __syncthreads();
    if (wid == 0) {
        float tv = (lane < 16) ? red[lane] : (isMax ? -3.4e38f : 0.0f);
        #pragma unroll
        for (int o = 8; o > 0; o >>= 1) {
            float u = __shfl_xor_sync(0xffffffffu, tv, o);
            tv = isMax ? fmaxf(tv, u) : (tv + u);
        }
        if (lane == 0) red[0] = tv;
    }
    __syncthreads();
    const float res = red[0];
    __syncthreads();
    return res;
}

__global__ void attn_kernel() {
    __shared__ float red[16];
    __shared__ int wcnt[16];
    __shared__ int woff[16];

    const int r = blockIdx.x;
    const int b = r >> 9, c = r & 511;
    const int d = threadIdx.x;
    const int lane = d & 31, wid = d >> 5;

    const float* S0 = g_S + ((size_t)b * M2 + c) * M2;
    const float* S1 = g_S + ((size_t)b * M2 + CCH + c) * M2;

    const float er = S0[d] - S1[CCH + d];
    const float ei = S0[CCH + d] + S1[d];

    const float mer = blkReduce(er, red, true);
    const float mei = blkReduce(ei, red, true);

    const float ar = mer - er;
    const float ai = mei - ei;
    const float s = ar * ar + ai * ai;

    const float smax = blkReduce(s, red, true);
    const float e = expf(s - smax);
    const float Z = blkReduce(e, red, false);
    const float w = e / Z;

    const bool keep = w > 1e-10f;
    const unsigned msk = __ballot_sync(0xffffffffu, keep);
    const int inpos = __popc(msk & ((1u << lane) - 1u));
    if (lane == 0) wcnt[wid] = __popc(msk);
    __syncthreads();
    if (d == 0) {
        int run = 0;
        #pragma unroll
        for (int i = 0; i < 16; i++) { woff[i] = run; run += wcnt[i]; }
        g_cnt[r] = run;
    }
    __syncthreads();
    if (keep) {
        const int pos = woff[wid] + inpos;
        g_idx[(size_t)r * CCH + pos] = (unsigned short)d;
        g_w[(size_t)r * CCH + pos] = w;
    }
}

// =======================================================================
// Kernel C: out = gamma * (sparse attention @ q) + x
// =======================================================================
__global__ __launch_bounds__(256) void apply_kernel(const float* __restrict__ x,
                                                    const float* __restrict__ gamma,
                                                    float* __restrict__ out) {
    const int r = blockIdx.x;
    const int b = r >> 9, c = r & 511;
    const int n = blockIdx.y * 1024 + threadIdx.x * 4;

    const int cnt = g_cnt[r];
    const float g = gamma[0];
    const size_t imagOff = (size_t)BATCH * CCH * KDIM;
    const float* xr = x;
    const float* xi = x + imagOff;

    float4 ar = make_float4(0.f, 0.f, 0.f, 0.f);
    float4 ai = make_float4(0.f, 0.f, 0.f, 0.f);
    const size_t lbase = (size_t)r * CCH;

    for (int i = 0; i < cnt; i++) {
        const int dch = g_idx[lbase + i];
        const float w = g_w[lbase + i];
        const size_t q = ((size_t)b * CCH + dch) * KDIM + n;
        const float4 qr = *(const float4*)(xr + q);
        const float4 qi = *(const float4*)(xi + q);
        ar.x += w * qr.x; ar.y += w * qr.y; ar.z += w * qr.z; ar.w += w * qr.w;
        ai.x += w * qi.x; ai.y += w * qi.y; ai.z += w * qi.z; ai.w += w * qi.w;
    }

    const size_t o = ((size_t)b * CCH + c) * KDIM + n;
    const float4 xrv = *(const float4*)(xr + o);
    const float4 xiv = *(const float4*)(xi + o);
    float4 orr = make_float4(g * ar.x + xrv.x, g * ar.y + xrv.y,
                             g * ar.z + xrv.z, g * ar.w + xrv.w);
    float4 oii = make_float4(g * ai.x + xiv.x, g * ai.y + xiv.y,
                             g * ai.z + xiv.z, g * ai.w + xiv.w);
    *(float4*)(out + o) = orr;
    *(float4*)(out + imagOff + o) = oii;
}

// =======================================================================
extern "C" void kernel_launch(void* const* d_in, const int* in_sizes, int n_in,
                              void* d_out, int out_size) {
    const float* x = (const float*)d_in[0];
    const float* gamma = (const float*)d_in[1];
    float* out = (float*)d_out;

    const int SMEM_DYN = 1024 + NSTAGES * STAGE_BYTES + 256;   // ~197.5 KB
    cudaFuncSetAttribute(syrk_tc_kernel, cudaFuncAttributeMaxDynamicSharedMemorySize, SMEM_DYN);

    split_kernel<<<(BATCH * 1024 * 1024) / 256, 256>>>(x);
    syrk_tc_kernel<<<dim3(NTILES * (NTILES + 1) / 2, BATCH), 256, SMEM_DYN>>>();
    attn_kernel<<<BATCH * CCH, 512>>>();
    apply_kernel<<<dim3(BATCH * CCH, 4), 256>>>(x, gamma, out);
}

// round 6
// speedup vs baseline: 1.9220x; 1.9220x over previous
#include <cuda_runtime.h>
#include <cuda_bf16.h>
#include <cstdint>
#include <cstddef>

#define BATCH 8
#define CCH   512
#define M2    1024          // 2*C rows of P
#define KDIM  4096
#define NTILES 8            // M2 / 128
#define NSTAGES 2
#define TILE_BYTES (128 * 128)          // 16KB: 128 rows x 128B (64 bf16), SW128 image
#define OPER_BYTES (3 * TILE_BYTES)     // h, m, l images packed contiguously (48KB)
#define STAGE_BYTES (2 * OPER_BYTES)    // A block + B block (96KB)
#define NKB   (KDIM / 64)               // 64 k-blocks of 64 bf16

// idesc kind::f16 (bf16 in): dtype F32 (1<<4) | atype BF16 (1<<7) | btype BF16 (1<<10)
//                          | (N/8)<<17 | (M/16)<<24, K-major both sides
#define IDESC_BF16 0x08200490u

// Arch-specific ('a') feature gate: tcgen05 only exists in the sm_103a SASS pass.
#if defined(__CUDA_ARCH__) && (defined(__CUDA_ARCH_FEAT_SM103_ALL) || defined(__CUDA_ARCH_FEAT_SM100_ALL) || defined(__CUDA_ARCH_FEAT_SM101_ALL) || defined(__CUDA_ARCH_FEAT_SM110_ALL))
#define TC_OK 1
#else
#define TC_OK 0
#endif

// ---------------- scratch (static device globals; no allocation) ----------------
// packed 3-level bf16 images: [b][rowblk(8)][kb(64)] -> 48KB block {h,m,l} of
// 128 rows x 64 bf16, each 16KB SW128-swizzled
__device__ uint32_t       g_pack[(size_t)BATCH * 8 * NKB * 12288];  // 192 MB
__device__ float          g_S[(size_t)BATCH * M2 * M2];             // 32 MB  S = P P^T
__device__ float          g_w[(size_t)BATCH * CCH * CCH];
__device__ unsigned short g_idx[(size_t)BATCH * CCH * CCH];
__device__ int            g_cnt[BATCH * CCH];

// ======================= helpers =======================
__device__ __forceinline__ uint32_t smem_u32(const void* p) {
    uint32_t a;
    asm("{ .reg .u64 t; cvta.to.shared.u64 t, %1; cvt.u32.u64 %0, t; }" : "=r"(a) : "l"(p));
    return a;
}

// =======================================================================
// Kernel 0: split fp32 -> 3 bf16 levels (h, m, l), written pre-tiled and
// pre-SW128-swizzled into contiguous 48KB {h,m,l} blocks per (rowblk, kb).
// Each thread: 8 consecutive elements -> 3 x 16B swizzled stores.
// =======================================================================
__global__ __launch_bounds__(256) void split_kernel(const float* __restrict__ x) {
    const size_t idx = (size_t)blockIdx.x * 256 + threadIdx.x;   // 8*1024*512 groups
    const int b   = (int)(idx >> 19);
    const int row = (int)((idx >> 9) & 1023);
    const int k8  = (int)(idx & 511);                            // group of 8 elems

    size_t src;
    if (row < CCH) src = ((size_t)b * CCH + row) * KDIM + (size_t)k8 * 8;
    else           src = ((size_t)(BATCH + b) * CCH + (row - CCH)) * KDIM + (size_t)k8 * 8;

    const float4 v0 = *(const float4*)(x + src);
    const float4 v1 = *(const float4*)(x + src + 4);
    float xv[8] = {v0.x, v0.y, v0.z, v0.w, v1.x, v1.y, v1.z, v1.w};

    unsigned short hs[8], ms[8], ls[8];
    #pragma unroll
    for (int i = 0; i < 8; i++) {
        const float xx = xv[i];
        const __nv_bfloat16 hb = __float2bfloat16_rn(xx);
        const float hf = __bfloat162float(hb);
        const float r1 = xx - hf;
        const __nv_bfloat16 mb = __float2bfloat16_rn(r1);
        const float mf = __bfloat162float(mb);
        const float r2 = r1 - mf;
        const __nv_bfloat16 lb = __float2bfloat16_rn(r2);
        hs[i] = __bfloat16_as_ushort(hb);
        ms[i] = __bfloat16_as_ushort(mb);
        ls[i] = __bfloat16_as_ushort(lb);
    }
    uint4 hv, mv, lv;
    hv.x = (uint32_t)hs[0] | ((uint32_t)hs[1] << 16);
    hv.y = (uint32_t)hs[2] | ((uint32_t)hs[3] << 16);
    hv.z = (uint32_t)hs[4] | ((uint32_t)hs[5] << 16);
    hv.w = (uint32_t)hs[6] | ((uint32_t)hs[7] << 16);
    mv.x = (uint32_t)ms[0] | ((uint32_t)ms[1] << 16);
    mv.y = (uint32_t)ms[2] | ((uint32_t)ms[3] << 16);
    mv.z = (uint32_t)ms[4] | ((uint32_t)ms[5] << 16);
    mv.w = (uint32_t)ms[6] | ((uint32_t)ms[7] << 16);
    lv.x = (uint32_t)ls[0] | ((uint32_t)ls[1] << 16);
    lv.y = (uint32_t)ls[2] | ((uint32_t)ls[3] << 16);
    lv.z = (uint32_t)ls[4] | ((uint32_t)ls[5] << 16);
    lv.w = (uint32_t)ls[6] | ((uint32_t)ls[7] << 16);

    const int rb = row >> 7, r = row & 127;
    const int kb = k8 >> 3;                               // 64 kbs of 64 elems
    const uint32_t byte_off = (uint32_t)r * 128u + (uint32_t)(k8 & 7) * 16u;
    const uint32_t sw = byte_off ^ ((byte_off >> 3) & 0x70u);
    char* base = (char*)g_pack + ((((size_t)b * 8 + rb) * NKB) + kb) * 49152 + sw;

    *(uint4*)(base)                 = hv;
    *(uint4*)(base + TILE_BYTES)    = mv;
    *(uint4*)(base + 2 * TILE_BYTES) = lv;
}

// =======================================================================
// Kernel A: tcgen05 bf16 6-term SYRK, 128x128 tile per CTA, 128 threads.
//   thread 0  : bulk-copy producer (one 48KB block per operand per stage)
//   thread 32 : MMA issuer (24 dispatches/stage)
//   warps 0-3 : TMEM epilogue + mirror
// =======================================================================
#if TC_OK
__device__ __forceinline__ void mbar_init(uint32_t a, uint32_t cnt) {
    asm volatile("mbarrier.init.shared.b64 [%0], %1;" :: "r"(a), "r"(cnt) : "memory");
}
__device__ __forceinline__ void mbar_inval(uint32_t a) {
    asm volatile("mbarrier.inval.shared.b64 [%0];" :: "r"(a) : "memory");
}
__device__ __forceinline__ void mbar_expect_tx(uint32_t a, uint32_t bytes) {
    asm volatile("mbarrier.arrive.expect_tx.shared.b64 _, [%0], %1;" :: "r"(a), "r"(bytes) : "memory");
}
__device__ __forceinline__ void mbar_wait(uint32_t a, uint32_t parity) {
    asm volatile(
        "{\n\t.reg .pred P;\n\t"
        "W%=:\n\t"
        "mbarrier.try_wait.parity.acquire.cta.shared::cta.b64 P, [%0], %1, 0x989680;\n\t"
        "@P bra.uni D%=;\n\t"
        "bra.uni W%=;\n\t"
        "D%=:\n\t}"
        :: "r"(a), "r"(parity) : "memory");
}
__device__ __forceinline__ void bulk_g2s(uint32_t dst, const void* src, uint32_t bytes, uint32_t mbar) {
    asm volatile(
        "cp.async.bulk.shared::cta.global.mbarrier::complete_tx::bytes [%0], [%1], %2, [%3];"
        :: "r"(dst), "l"(src), "r"(bytes), "r"(mbar) : "memory");
}
__device__ __forceinline__ uint64_t make_desc_sw128(uint32_t addr) {
    return ((uint64_t)2 << 61) | ((uint64_t)1 << 46) | ((uint64_t)64 << 32) |
           ((uint64_t)1 << 16) | (((uint64_t)(addr >> 4)) & 0x3FFF);
}
__device__ __forceinline__ void mma_bf16_ss(uint32_t d, uint64_t ad, uint64_t bd, uint32_t en) {
    asm volatile(
        "{\n\t.reg .pred p;\n\t"
        "setp.ne.u32 p, %4, 0;\n\t"
        "tcgen05.mma.cta_group::1.kind::f16 [%0], %1, %2, %3, {%5,%5,%5,%5}, p;\n\t}"
        :: "r"(d), "l"(ad), "l"(bd), "r"(IDESC_BF16), "r"(en), "r"(0u) : "memory");
}
__device__ __forceinline__ void tc_commit(uint32_t mbar) {
    asm volatile(
        "tcgen05.commit.cta_group::1.mbarrier::arrive::one.shared::cluster.b64 [%0];"
        :: "r"(mbar) : "memory");
}
#endif

__global__ __launch_bounds__(128, 1) void syrk_tc_kernel() {
#if TC_OK
    extern __shared__ char smem[];
    const uint32_t sb = smem_u32(smem);
    const uint32_t tb = (sb + 1023u) & ~1023u;            // 1024-aligned tile base
    const uint32_t ctl = tb + NSTAGES * STAGE_BYTES;      // control area
    const uint32_t mb_full  = ctl + 16;                   // 2 x 8B
    const uint32_t mb_empty = ctl + 16 + 16;              // 2 x 8B
    const uint32_t mb_done  = ctl + 16 + 32;

    const int tid = threadIdx.x;
    const int wid = tid >> 5, lid = tid & 31;

    const int b = blockIdx.y;
    int ti = 0, rem = blockIdx.x;
    while (rem >= NTILES - ti) { rem -= NTILES - ti; ti++; }
    const int tj = ti + rem;
    const bool diag = (ti == tj);

    if (wid == 0) {
        asm volatile("tcgen05.alloc.cta_group::1.sync.aligned.shared::cta.b32 [%0], %1;"
                     :: "r"(ctl), "r"(128u) : "memory");
    }
    if (tid == 0) {
        for (int s = 0; s < NSTAGES; s++) { mbar_init(mb_full + s * 8, 1); mbar_init(mb_empty + s * 8, 1); }
        mbar_init(mb_done, 1);
        asm volatile("fence.proxy.async.shared::cta;" ::: "memory");
    }
    __syncthreads();

    uint32_t tmem;
    asm volatile("ld.shared.b32 %0, [%1];" : "=r"(tmem) : "r"(ctl));

    const uint32_t txbytes = diag ? OPER_BYTES : (2 * OPER_BYTES);

    if (tid == 0) {
        // ---------------- producer: one 48KB block per operand ----------------
        const char* tiA = (const char*)g_pack + (((size_t)b * 8 + ti) * NKB) * 49152;
        const char* tiB = (const char*)g_pack + (((size_t)b * 8 + tj) * NKB) * 49152;
        int ph[NSTAGES] = {0, 0};
        for (int kb = 0; kb < NKB; kb++) {
            const int s = kb & 1;
            if (kb >= NSTAGES) { mbar_wait(mb_empty + s * 8, ph[s]); ph[s] ^= 1; }
            const uint32_t st = tb + s * STAGE_BYTES;
            const uint32_t fb = mb_full + s * 8;
            mbar_expect_tx(fb, txbytes);
            bulk_g2s(st, tiA + (size_t)kb * 49152, OPER_BYTES, fb);
            if (!diag)
                bulk_g2s(st + OPER_BYTES, tiB + (size_t)kb * 49152, OPER_BYTES, fb);
        }
    } else if (tid == 32) {
        // ---------------- MMA issuer ----------------
        int ph[NSTAGES] = {0, 0};
        uint32_t en = 0;
        for (int kb = 0; kb < NKB; kb++) {
            const int s = kb & 1;
            mbar_wait(mb_full + s * 8, ph[s]); ph[s] ^= 1;
            const uint32_t st = tb + s * STAGE_BYTES;
            const uint64_t dAh = make_desc_sw128(st);
            const uint64_t dAm = make_desc_sw128(st + TILE_BYTES);
            const uint64_t dAl = make_desc_sw128(st + 2 * TILE_BYTES);
            const uint64_t dBh = diag ? dAh : make_desc_sw128(st + OPER_BYTES);
            const uint64_t dBm = diag ? dAm : make_desc_sw128(st + OPER_BYTES + TILE_BYTES);
            const uint64_t dBl = diag ? dAl : make_desc_sw128(st + OPER_BYTES + 2 * TILE_BYTES);
            #pragma unroll
            for (int k = 0; k < 4; k++) {    // 4 k-steps of 16 bf16 (32B = +2 units)
                const uint64_t o = k * 2;
                mma_bf16_ss(tmem, dAh + o, dBh + o, en); en = 1;
                mma_bf16_ss(tmem, dAh + o, dBm + o, 1);
                mma_bf16_ss(tmem, dAm + o, dBh + o, 1);
                mma_bf16_ss(tmem, dAm + o, dBm + o, 1);
                mma_bf16_ss(tmem, dAh + o, dBl + o, 1);
                mma_bf16_ss(tmem, dAl + o, dBh + o, 1);
            }
            tc_commit(mb_empty + s * 8);
        }
        tc_commit(mb_done);
    }

    // ---------------- epilogue ----------------
    mbar_wait(mb_done, 0);
    asm volatile("tcgen05.fence::after_thread_sync;" ::: "memory");

    const size_t Sb = (size_t)b * M2 * M2;
    const int r0 = ti * 128, c0 = tj * 128;
    const int row = r0 + wid * 32 + lid;

    for (int cb = 0; cb < 4; cb++) {
        uint32_t d[32];
        asm volatile(
            "tcgen05.ld.sync.aligned.32x32b.x32.b32 "
            "{%0,%1,%2,%3,%4,%5,%6,%7,%8,%9,%10,%11,%12,%13,%14,%15,"
            "%16,%17,%18,%19,%20,%21,%22,%23,%24,%25,%26,%27,%28,%29,%30,%31}, [%32];"
            : "=r"(d[0]), "=r"(d[1]), "=r"(d[2]), "=r"(d[3]), "=r"(d[4]), "=r"(d[5]), "=r"(d[6]), "=r"(d[7]),
              "=r"(d[8]), "=r"(d[9]), "=r"(d[10]), "=r"(d[11]), "=r"(d[12]), "=r"(d[13]), "=r"(d[14]), "=r"(d[15]),
              "=r"(d[16]), "=r"(d[17]), "=r"(d[18]), "=r"(d[19]), "=r"(d[20]), "=r"(d[21]), "=r"(d[22]), "=r"(d[23]),
              "=r"(d[24]), "=r"(d[25]), "=r"(d[26]), "=r"(d[27]), "=r"(d[28]), "=r"(d[29]), "=r"(d[30]), "=r"(d[31])
            : "r"(tmem + cb * 32));
        asm volatile("tcgen05.wait::ld.sync.aligned;" ::: "memory");

        float* dst = g_S + Sb + (size_t)row * M2 + c0 + cb * 32;
        #pragma unroll
        for (int q = 0; q < 8; q++) {
            float4 v = make_float4(__uint_as_float(d[q * 4 + 0]), __uint_as_float(d[q * 4 + 1]),
                                   __uint_as_float(d[q * 4 + 2]), __uint_as_float(d[q * 4 + 3]));
            *(float4*)(dst + q * 4) = v;
        }
        if (!diag) {
            #pragma unroll
            for (int j = 0; j < 32; j++)
                g_S[Sb + (size_t)(c0 + cb * 32 + j) * M2 + row] = __uint_as_float(d[j]);
        }
    }

    __syncthreads();
    if (tid == 0) {
        for (int s = 0; s < NSTAGES; s++) { mbar_inval(mb_full + s * 8); mbar_inval(mb_empty + s * 8); }
        mbar_inval(mb_done);
    }
    __syncthreads();
    if (wid == 0) {
        asm volatile("tcgen05.dealloc.cta_group::1.sync.aligned.b32 %0, %1;" :: "r"(tmem), "r"(128u));
    }
#endif
}

// =======================================================================
// Kernel B: softmax of (max-er)^2+(max-ei)^2 over S rows + compaction
// =======================================================================
__device__ __forceinline__ float blkReduce(float v, float* red, bool isMax) {
    #pragma unroll
    for (int o = 16; o > 0; o >>= 1) {
        float tv = __shfl_xor_sync(0xffffffffu, v, o);
        v = isMax ? fmaxf(v, tv) : (v + tv);
    }
    const int lane = threadIdx.x & 31, wid = threadIdx.x >> 5;
    if (lane == 0) red[wid] = v;
    __syncthreads();
    if (wid == 0) {
        float tv = (lane < 16) ? red[lane] : (isMax ? -3.4e38f : 0.0f);
        #pragma unroll
        for (int o = 8; o > 0; o >>= 1) {
            float u = __shfl_xor_sync(0xffffffffu, tv, o);
            tv = isMax ? fmaxf(tv, u) : (tv + u);
        }
        if (lane == 0) red[0] = tv;
    }
    __syncthreads();
    const float res = red[0];
    __syncthreads();
    return res;
}

__global__ void attn_kernel() {
    __shared__ float red[16];
    __shared__ int wcnt[16];
    __shared__ int woff[16];

    const int r = blockIdx.x;
    const int b = r >> 9, c = r & 511;
    const int d = threadIdx.x;
    const int lane = d & 31, wid = d >> 5;

    const float* S0 = g_S + ((size_t)b * M2 + c) * M2;
    const float* S1 = g_S + ((size_t)b * M2 + CCH + c) * M2;

    const float er = S0[d] - S1[CCH + d];
    const float ei = S0[CCH + d] + S1[d];

    const float mer = blkReduce(er, red, true);
    const float mei = blkReduce(ei, red, true);

    const float ar = mer - er;
    const float ai = mei - ei;
    const float s = ar * ar + ai * ai;

    const float smax = blkReduce(s, red, true);
    const float e = expf(s - smax);
    const float Z = blkReduce(e, red, false);
    const float w = e / Z;

    const bool keep = w > 1e-10f;
    const unsigned msk = __ballot_sync(0xffffffffu, keep);
    const int inpos = __popc(msk & ((1u << lane) - 1u));
    if (lane == 0) wcnt[wid] = __popc(msk);
    __syncthreads();
    if (d == 0) {
        int run = 0;
        #pragma unroll
        for (int i = 0; i < 16; i++) { woff[i] = run; run += wcnt[i]; }
        g_cnt[r] = run;
    }
    __syncthreads();
    if (keep) {
        const int pos = woff[wid] + inpos;
        g_idx[(size_t)r * CCH + pos] = (unsigned short)d;
        g_w[(size_t)r * CCH + pos] = w;
    }
}

// =======================================================================
// Kernel C: out = gamma * (sparse attention @ q) + x
// =======================================================================
__global__ __launch_bounds__(256) void apply_kernel(const float* __restrict__ x,
                                                    const float* __restrict__ gamma,
                                                    float* __restrict__ out) {
    const int r = blockIdx.x;
    const int b = r >> 9, c = r & 511;
    const int n = blockIdx.y * 1024 + threadIdx.x * 4;

    const int cnt = g_cnt[r];
    const float g = gamma[0];
    const size_t imagOff = (size_t)BATCH * CCH * KDIM;
    const float* xr = x;
    const float* xi = x + imagOff;

    float4 ar = make_float4(0.f, 0.f, 0.f, 0.f);
    float4 ai = make_float4(0.f, 0.f, 0.f, 0.f);
    const size_t lbase = (size_t)r * CCH;

    for (int i = 0; i < cnt; i++) {
        const int dch = g_idx[lbase + i];
        const float w = g_w[lbase + i];
        const size_t q = ((size_t)b * CCH + dch) * KDIM + n;
        const float4 qr = *(const float4*)(xr + q);
        const float4 qi = *(const float4*)(xi + q);
        ar.x += w * qr.x; ar.y += w * qr.y; ar.z += w * qr.z; ar.w += w * qr.w;
        ai.x += w * qi.x; ai.y += w * qi.y; ai.z += w * qi.z; ai.w += w * qi.w;
    }

    const size_t o = ((size_t)b * CCH + c) * KDIM + n;
    const float4 xrv = *(const float4*)(xr + o);
    const float4 xiv = *(const float4*)(xi + o);
    float4 orr = make_float4(g * ar.x + xrv.x, g * ar.y + xrv.y,
                             g * ar.z + xrv.z, g * ar.w + xrv.w);
    float4 oii = make_float4(g * ai.x + xiv.x, g * ai.y + xiv.y,
                             g * ai.z + xiv.z, g * ai.w + xiv.w);
    *(float4*)(out + o) = orr;
    *(float4*)(out + imagOff + o) = oii;
}

// =======================================================================
extern "C" void kernel_launch(void* const* d_in, const int* in_sizes, int n_in,
                              void* d_out, int out_size) {
    const float* x = (const float*)d_in[0];
    const float* gamma = (const float*)d_in[1];
    float* out = (float*)d_out;

    const int SMEM_DYN = 1024 + NSTAGES * STAGE_BYTES + 256;   // ~193.5 KB
    cudaFuncSetAttribute(syrk_tc_kernel, cudaFuncAttributeMaxDynamicSharedMemorySize, SMEM_DYN);

    split_kernel<<<(BATCH * 1024 * 512) / 256, 256>>>(x);
    syrk_tc_kernel<<<dim3(NTILES * (NTILES + 1) / 2, BATCH), 128, SMEM_DYN>>>();
    attn_kernel<<<BATCH * CCH, 512>>>();
    apply_kernel<<<dim3(BATCH * CCH, 4), 256>>>(x, gamma, out);
}